// round 1
// baseline (speedup 1.0000x reference)
#include <cuda_runtime.h>
#include <cuda_fp16.h>

// Problem constants (fixed by setup_inputs)
#define BATCH 4
#define NPTS  8192
#define NEDGE 262144
#define CIN   32
#define COUT  32
#define NH    16
#define TOTAL_EDGES (BATCH * NEDGE)
#define UROW  (COUT * NH)          // 512 halves per point
#define GAMMA 4.0f

// Scratch: transformed features u[b,p,o,h] in fp16 (33.5 MB) + transposed W
__device__ __align__(16) __half g_u[(size_t)BATCH * NPTS * UROW];
__device__ float g_Wt[CIN * COUT * NH];   // Wt[i][o][h] = W[h][o][i] * rsqrt(n_norm)

// ---------------------------------------------------------------------------
// Kernel 1: transpose W into [i][o][h] layout (coalesced reads in transform)
// and fold in the 1/sqrt(n_norm) normalization.
// ---------------------------------------------------------------------------
__global__ void k_transposeW(const float* __restrict__ W,
                             const int* __restrict__ n_norm) {
    int t = blockIdx.x * blockDim.x + threadIdx.x;   // 0..16383
    if (t >= CIN * COUT * NH) return;
    int n = *n_norm;
    float scale = (n > 0) ? rsqrtf((float)n) : 1.0f;
    int i   = t >> 9;          // /512
    int rem = t & 511;
    int o   = rem >> 4;
    int h   = rem & 15;
    g_Wt[t] = W[(h * COUT + o) * CIN + i] * scale;
}

// ---------------------------------------------------------------------------
// Kernel 2: transform  u[b,p,o,h] = sum_i Wt[i,o,h] * x[b,p,i]   (fp16 out)
// 512 threads = one (o,h) column each; PTS points per block; W column held in
// registers, x tile in smem read as float4 broadcasts.
// ---------------------------------------------------------------------------
#define PTS 8
__global__ __launch_bounds__(512) void k_transform(const float* __restrict__ feat) {
    __shared__ float xs[PTS * CIN];          // 1 KB
    const int t = threadIdx.x;               // 0..511  == o*16+h
    const size_t base_pt = (size_t)blockIdx.x * PTS;

    if (t < PTS * CIN) xs[t] = feat[base_pt * CIN + t];
    __syncthreads();

    float w[CIN];
#pragma unroll
    for (int i = 0; i < CIN; i++) w[i] = g_Wt[i * 512 + t];

    const float4* xs4 = (const float4*)xs;
    __half* uout = g_u + base_pt * UROW + t;
#pragma unroll
    for (int p = 0; p < PTS; p++) {
        float acc = 0.0f;
#pragma unroll
        for (int j = 0; j < CIN / 4; j++) {
            float4 xv = xs4[p * (CIN / 4) + j];
            acc = fmaf(w[4 * j + 0], xv.x, acc);
            acc = fmaf(w[4 * j + 1], xv.y, acc);
            acc = fmaf(w[4 * j + 2], xv.z, acc);
            acc = fmaf(w[4 * j + 3], xv.w, acc);
        }
        uout[(size_t)p * UROW] = __float2half_rn(acc);
    }
}

// ---------------------------------------------------------------------------
// Kernel 3: edge stage. One warp per edge, lane = output channel.
//   rbf[h] computed by lanes (h = lane&15, upper half redundant but benign),
//   broadcast through ping-pong smem; u row gathered as 2x LDG.128 per lane
//   (1 KB coalesced); 32-lane coalesced fp32 atomicAdd scatter.
// ---------------------------------------------------------------------------
__global__ __launch_bounds__(256) void k_edges(const float* __restrict__ evec,
                                               const int*   __restrict__ esrc,
                                               const int*   __restrict__ edst,
                                               const float* __restrict__ mu,
                                               float*       __restrict__ out) {
    __shared__ float srbf[2][8][16];
    const int lane = threadIdx.x & 31;
    const int w    = threadIdx.x >> 5;
    const int gw   = blockIdx.x * 8 + w;
    const int nwarps = gridDim.x * 8;
    const float muv = __ldg(&mu[lane & 15]);
    int pp = 0;

    for (int e = gw; e < TOTAL_EDGES; e += nwarps) {
        // uniform (broadcast) loads
        const float vx = __ldg(&evec[3 * (size_t)e + 0]);
        const float vy = __ldg(&evec[3 * (size_t)e + 1]);
        const float vz = __ldg(&evec[3 * (size_t)e + 2]);
        const int src = __ldg(&esrc[e]);
        const int dst = __ldg(&edst[e]);

        const float r = sqrtf(fmaf(vx, vx, fmaf(vy, vy, vz * vz)));
        const float d = r - muv;
        const float rb = __expf(-GAMMA * d * d);
        srbf[pp][w][lane & 15] = rb;     // lanes 16-31 write identical values
        __syncwarp();
        const float4 R0 = *(const float4*)&srbf[pp][w][0];
        const float4 R1 = *(const float4*)&srbf[pp][w][4];
        const float4 R2 = *(const float4*)&srbf[pp][w][8];
        const float4 R3 = *(const float4*)&srbf[pp][w][12];
        pp ^= 1;

        const int b = e >> 18;                       // e / NEDGE
        const size_t row = ((size_t)(b * NPTS) + src) * UROW;
        const uint4* up = (const uint4*)(g_u + row) + lane * 2;
        const uint4 a0 = up[0];
        const uint4 a1 = up[1];

        float acc = 0.0f;
        const __half2* p0 = (const __half2*)&a0;
        const __half2* p1 = (const __half2*)&a1;
        float2 f;
        f = __half22float2(p0[0]); acc = fmaf(R0.x, f.x, fmaf(R0.y, f.y, acc));
        f = __half22float2(p0[1]); acc = fmaf(R0.z, f.x, fmaf(R0.w, f.y, acc));
        f = __half22float2(p0[2]); acc = fmaf(R1.x, f.x, fmaf(R1.y, f.y, acc));
        f = __half22float2(p0[3]); acc = fmaf(R1.z, f.x, fmaf(R1.w, f.y, acc));
        f = __half22float2(p1[0]); acc = fmaf(R2.x, f.x, fmaf(R2.y, f.y, acc));
        f = __half22float2(p1[1]); acc = fmaf(R2.z, f.x, fmaf(R2.w, f.y, acc));
        f = __half22float2(p1[2]); acc = fmaf(R3.x, f.x, fmaf(R3.y, f.y, acc));
        f = __half22float2(p1[3]); acc = fmaf(R3.z, f.x, fmaf(R3.w, f.y, acc));

        atomicAdd(&out[((size_t)(b * NPTS) + dst) * COUT + lane], acc);
    }
}

// ---------------------------------------------------------------------------
// Launch: transposeW -> transform -> memset(out) -> edges (default stream)
// ---------------------------------------------------------------------------
extern "C" void kernel_launch(void* const* d_in, const int* in_sizes, int n_in,
                              void* d_out, int out_size) {
    const float* features = (const float*)d_in[0];
    const float* edge_vec = (const float*)d_in[1];
    const float* W        = (const float*)d_in[2];
    const float* mu       = (const float*)d_in[3];
    const int*   edge_src = (const int*)d_in[4];
    const int*   edge_dst = (const int*)d_in[5];
    const int*   n_norm   = (const int*)d_in[6];
    float* out = (float*)d_out;

    (void)in_sizes; (void)n_in;

    k_transposeW<<<(CIN * COUT * NH + 511) / 512, 512>>>(W, n_norm);
    k_transform<<<(BATCH * NPTS) / PTS, 512>>>(features);
    cudaMemsetAsync(out, 0, (size_t)out_size * sizeof(float), 0);
    k_edges<<<148 * 8, 256>>>(edge_vec, edge_src, edge_dst, mu, out);
}